// round 15
// baseline (speedup 1.0000x reference)
#include <cuda_runtime.h>

#define BB 512
#define TT 512
#define IN_DIM 256
#define NJ 32          // 4 gates * 8 qubits
#define DTOT 264
#define ROWS (BB*TT)

// scratch: per (row, j=q*4+g): cos(pre) at [row][j], sin(pre) at [row][32+j]
// pre = x.W + bias + theta  (everything except the recurrent Wh.h term)
__device__ float g_trig[(size_t)ROWS * 64];

typedef unsigned long long ull;
typedef unsigned int uint;

__device__ __forceinline__ ull pack2(float lo, float hi) {
    ull r;
    asm("mov.b64 %0, {%1, %2};" : "=l"(r) : "r"(__float_as_uint(lo)), "r"(__float_as_uint(hi)));
    return r;
}
__device__ __forceinline__ ull fma2(ull a, ull b, ull c) {
    ull d;
    asm("fma.rn.f32x2 %0, %1, %2, %3;" : "=l"(d) : "l"(a), "l"(b), "l"(c));
    return d;
}
__device__ __forceinline__ float lo2(ull v) { return __uint_as_float((uint)(v & 0xffffffffull)); }
__device__ __forceinline__ float hi2(ull v) { return __uint_as_float((uint)(v >> 32)); }

// ---------------- GEMM + trig epilogue ------------------------------------------
// 256 threads, 2 rows/thread, real distance-3 prefetch (4-slot modular buffer).
// Epilogue: pre = acc + bias + theta, then store cos(pre), sin(pre) to g_trig.
__global__ void __launch_bounds__(256) gemm_kernel(
    const float* __restrict__ x,
    const float* __restrict__ Wf, const float* __restrict__ bf,
    const float* __restrict__ Wi, const float* __restrict__ bi,
    const float* __restrict__ Wg, const float* __restrict__ bg,
    const float* __restrict__ Wo, const float* __restrict__ bo,
    const float* __restrict__ thetas)
{
    __shared__ __align__(16) float ws[IN_DIM * NJ];     // [k][q*4+g], 32 KB
    __shared__ float bts[NJ];
    const int tid = threadIdx.x;

    for (int e = tid; e < IN_DIM * NJ; e += 256) {
        int k = e >> 5, j = e & 31;
        int q = j >> 2, g = j & 3;
        const float* Wp = (g == 0) ? Wf : (g == 1) ? Wi : (g == 2) ? Wg : Wo;
        ws[e] = Wp[q * DTOT + k];
    }
    if (tid < NJ) {
        int q = tid >> 2, g = tid & 3;
        const float* bp = (g == 0) ? bf : (g == 1) ? bi : (g == 2) ? bg : bo;
        bts[tid] = bp[q] + thetas[g * 8 + q];
    }
    __syncthreads();

    const size_t row0 = (size_t)blockIdx.x * 512 + tid;   // second row: row0 + 256
    const float4* x0 = reinterpret_cast<const float4*>(x + row0 * IN_DIM);
    const float4* x1 = reinterpret_cast<const float4*>(x + (row0 + 256) * IN_DIM);

    ull acc0[16], acc1[16];
    #pragma unroll
    for (int p = 0; p < 16; p++) { acc0[p] = 0ull; acc1[p] = 0ull; }

    // 4-slot prefetch buffers, slot = k4 & 3
    float4 abuf[4], bbuf[4];
    abuf[0] = x0[0]; bbuf[0] = x1[0];
    abuf[1] = x0[1]; bbuf[1] = x1[1];
    abuf[2] = x0[2]; bbuf[2] = x1[2];

    const int NK4 = IN_DIM / 4;   // 64
    for (int k40 = 0; k40 < NK4; k40 += 4) {
        #pragma unroll
        for (int u = 0; u < 4; u++) {
            const int k4 = k40 + u;
            float4 a = abuf[u];
            float4 b = bbuf[u];
            int kn = k4 + 3; kn = (kn > NK4 - 1) ? (NK4 - 1) : kn;
            abuf[(u + 3) & 3] = x0[kn];
            bbuf[(u + 3) & 3] = x1[kn];

            float xa[4] = {a.x, a.y, a.z, a.w};
            float xb[4] = {b.x, b.y, b.z, b.w};
            #pragma unroll
            for (int kk = 0; kk < 4; kk++) {
                const double2* wv = reinterpret_cast<const double2*>(ws + (k4 * 4 + kk) * NJ);
                ull pa = pack2(xa[kk], xa[kk]);
                ull pb = pack2(xb[kk], xb[kk]);
                #pragma unroll
                for (int p4 = 0; p4 < 8; p4++) {
                    double2 wd = wv[p4];
                    ull w0 = (ull)__double_as_longlong(wd.x);
                    ull w1 = (ull)__double_as_longlong(wd.y);
                    acc0[2*p4]   = fma2(pa, w0, acc0[2*p4]);
                    acc0[2*p4+1] = fma2(pa, w1, acc0[2*p4+1]);
                    acc1[2*p4]   = fma2(pb, w0, acc1[2*p4]);
                    acc1[2*p4+1] = fma2(pb, w1, acc1[2*p4+1]);
                }
            }
        }
    }

    // epilogue: pre -> (cos, sin) -> g_trig
    #pragma unroll
    for (int r = 0; r < 2; r++) {
        const ull* acc = (r == 0) ? acc0 : acc1;
        size_t row = row0 + (size_t)r * 256;
        float co[32], si[32];
        #pragma unroll
        for (int i = 0; i < 16; i++) {
            float p0 = lo2(acc[i]) + bts[2*i];
            float p1 = hi2(acc[i]) + bts[2*i+1];
            __sincosf(p0, &si[2*i],   &co[2*i]);
            __sincosf(p1, &si[2*i+1], &co[2*i+1]);
        }
        float4* tv = reinterpret_cast<float4*>(g_trig + row * 64);
        #pragma unroll
        for (int p4 = 0; p4 < 8; p4++) {
            tv[p4]     = make_float4(co[4*p4], co[4*p4+1], co[4*p4+2], co[4*p4+3]);
            tv[8 + p4] = make_float4(si[4*p4], si[4*p4+1], si[4*p4+2], si[4*p4+3]);
        }
    }
}

// ---------------- activations: pure FMA / one RCP, valid on proven input ranges ----
// sigmoid(x), |x|<=1: 0.5 + x*poly(x^2), odd Taylor deg 9, err < 2.2e-6
__device__ __forceinline__ float sigp(float x) {
    float u = x * x;
    float p = fmaf(u, 2.1356922e-5f, -2.1081349e-4f);
    p = fmaf(u, p, 2.0833334e-3f);
    p = fmaf(u, p, -2.0833334e-2f);
    p = fmaf(u, p, 0.25f);
    return fmaf(x, p, 0.5f);
}
// tanh(x), |x|<=2.1: Pade x*(945+105u+u^2)/(945+420u+15u^2), err <= 7e-5
__device__ __forceinline__ float tanhp(float x) {
    float u = x * x;
    float N = fmaf(u, u + 105.0f, 945.0f);
    float D = fmaf(u, fmaf(15.0f, u, 420.0f), 945.0f);
    return __fdividef(x * N, D);
}

// ---------------- recurrence -------------------------------------------------------
// One warp per 4 batches, lane = sub*8 + qubit.
// hx exchanged via shfl (no barrier); cosines exchanged via double-buffered smem with
// ONE __syncwarp per step. cos(pre+delta) computed from precomputed (cp, sp) and
// small-angle polys for delta (|delta| <= 0.49) -- no MUFU on the recurrent chain.
#define CS_STRIDE 36   // floats per sub-batch in cs[] (144B)

__global__ void __launch_bounds__(32) recur_kernel(
    const float* __restrict__ Wf, const float* __restrict__ Wi,
    const float* __restrict__ Wg, const float* __restrict__ Wo,
    float* __restrict__ out)
{
    __shared__ __align__(16) float cs[2][4 * CS_STRIDE];   // [parity][sub][qubit][gate]

    const unsigned FULL = 0xffffffffu;
    const int lane = threadIdx.x;
    const int q   = lane & 7;
    const int sub = lane >> 3;
    const int wg  = blockIdx.x * 4 + sub;   // batch index

    const float* Wptr[4] = {Wf, Wi, Wg, Wo};
    float wh[4][8];
    #pragma unroll
    for (int g = 0; g < 4; g++)
        #pragma unroll
        for (int k = 0; k < 8; k++) wh[g][k] = Wptr[g][q * DTOT + IN_DIM + k];

    // lane-constant product masks: include c_k iff (k<=q) or (q==0 and k>=1)
    const bool q0 = (q == 0);
    bool inc[8];
    #pragma unroll
    for (int k = 1; k < 8; k++) inc[k] = (k <= q) || q0;

    // trig stream: per t, cos at [t*16 + q], sin at [t*16 + 8 + q] (float4 units)
    const float4* pr = reinterpret_cast<const float4*>(g_trig + (size_t)wg * TT * 64);
    float4 cbuf[4], sbuf[4];
    #pragma unroll
    for (int i = 0; i < 3; i++) {
        cbuf[i] = pr[i * 16 + q];
        sbuf[i] = pr[i * 16 + 8 + q];
    }

    float hx = 0.f, cx = 0.f;
    float* outp = out + (size_t)wg * TT * 8 + q;

    float* myc0 = &cs[0][sub * CS_STRIDE + q * 4];
    float* myc1 = &cs[1][sub * CS_STRIDE + q * 4];
    const float4* grp0 = reinterpret_cast<const float4*>(&cs[0][sub * CS_STRIDE]);
    const float4* grp1 = reinterpret_cast<const float4*>(&cs[1][sub * CS_STRIDE]);

    for (int t0 = 0; t0 < TT; t0 += 4) {
        #pragma unroll
        for (int u = 0; u < 4; u++) {
            const int t = t0 + u;
            float4 cp = cbuf[u];
            float4 sp = sbuf[u];
            int tn = t + 3; tn = (tn > TT - 1) ? (TT - 1) : tn;
            cbuf[(u + 3) & 3] = pr[tn * 16 + q];
            sbuf[(u + 3) & 3] = pr[tn * 16 + 8 + q];

            // hidden state via shfl (no barrier)
            float hv[8];
            #pragma unroll
            for (int k = 0; k < 8; k++) hv[k] = __shfl_sync(FULL, hx, k, 8);

            // delta_g = Wh_g . hv   (|delta| <= 0.49)
            float dl[4];
            #pragma unroll
            for (int g = 0; g < 4; g++) {
                float s0 = fmaf(wh[g][0], hv[0], fmaf(wh[g][2], hv[2],
                           fmaf(wh[g][4], hv[4], wh[g][6] * hv[6])));
                float s1 = fmaf(wh[g][1], hv[1], fmaf(wh[g][3], hv[3],
                           fmaf(wh[g][5], hv[5], wh[g][7] * hv[7])));
                dl[g] = s0 + s1;
            }

            // c_g = cp*cos(dl) - sp*sin(dl), small-angle Taylor (err < 1e-7)
            float cpa[4] = {cp.x, cp.y, cp.z, cp.w};
            float spa[4] = {sp.x, sp.y, sp.z, sp.w};
            float cw[4];
            #pragma unroll
            for (int g = 0; g < 4; g++) {
                float d  = dl[g];
                float uu = d * d;
                float cd = fmaf(uu, fmaf(uu, fmaf(uu, -1.3888889e-3f, 4.1666668e-2f), -0.5f), 1.0f);
                float sd = d * fmaf(uu, fmaf(uu, fmaf(uu, -1.9841270e-4f, 8.3333333e-3f), -0.16666667f), 1.0f);
                cw[g] = fmaf(cpa[g], cd, -spa[g] * sd);
            }

            // publish my 4 cosines (parity buffer), one sync, read all 8 qubits'
            float* myc = (u & 1) ? myc1 : myc0;
            *reinterpret_cast<float4*>(myc) = make_float4(cw[0], cw[1], cw[2], cw[3]);
            __syncwarp();
            const float4* grpc = (u & 1) ? grp1 : grp0;
            float4 cq[8];
            #pragma unroll
            for (int k = 0; k < 8; k++) cq[k] = grpc[k];

            // m = (q==0 ? 1 : c_0) * prod_{k>=1, inc[k]} c_k
            float m[4];
            #pragma unroll
            for (int g = 0; g < 4; g++) {
                float ck[8];
                ck[0] = (g == 0) ? cq[0].x : (g == 1) ? cq[0].y : (g == 2) ? cq[0].z : cq[0].w;
                #pragma unroll
                for (int k = 1; k < 8; k++) {
                    float v = (g == 0) ? cq[k].x : (g == 1) ? cq[k].y : (g == 2) ? cq[k].z : cq[k].w;
                    ck[k] = inc[k] ? v : 1.0f;
                }
                float head = q0 ? 1.0f : ck[0];
                float t01 = ck[1] * ck[2];
                float t23 = ck[3] * ck[4];
                float t45 = ck[5] * ck[6];
                m[g] = (head * t01) * (t23 * (t45 * ck[7]));
            }

            // gates: |m|<=1 guaranteed
            float f_ = sigp(m[0]);
            float i_ = sigp(m[1]);
            float gg = tanhp(m[2]);
            float o_ = sigp(m[3]);

            cx = fmaf(f_, cx, i_ * gg);          // |cx| <= 2.07
            hx = o_ * tanhp(cx);

            outp[(size_t)t * 8] = hx;
        }
    }

    out[(size_t)BB * TT * 8 + (size_t)wg * 8 + q] = hx;                        // final hx
    out[(size_t)BB * TT * 8 + (size_t)BB * 8 + (size_t)wg * 8 + q] = cx;       // final cx
}

extern "C" void kernel_launch(void* const* d_in, const int* in_sizes, int n_in,
                              void* d_out, int out_size) {
    (void)in_sizes; (void)n_in; (void)out_size;
    const float* x  = (const float*)d_in[0];
    const float* Wf = (const float*)d_in[1]; const float* bf = (const float*)d_in[2];
    const float* Wi = (const float*)d_in[3]; const float* bi = (const float*)d_in[4];
    const float* Wg = (const float*)d_in[5]; const float* bg = (const float*)d_in[6];
    const float* Wo = (const float*)d_in[7]; const float* bo = (const float*)d_in[8];
    const float* th = (const float*)d_in[9];
    float* out = (float*)d_out;

    gemm_kernel<<<ROWS / 512, 256>>>(x, Wf, bf, Wi, bi, Wg, bg, Wo, bo, th);
    recur_kernel<<<BB / 4, 32>>>(Wf, Wi, Wg, Wo, out);
}

// round 16
// speedup vs baseline: 1.2166x; 1.2166x over previous
#include <cuda_runtime.h>

#define BB 512
#define TT 512
#define IN_DIM 256
#define NJ 32          // 4 gates * 8 qubits
#define DTOT 264
#define ROWS (BB*TT)

// scratch: input projection, layout [row][q*4+g]  (q = qubit, g = gate f,i,g,o)
__device__ float g_proj[(size_t)ROWS * NJ];

typedef unsigned long long ull;
typedef unsigned int uint;

__device__ __forceinline__ ull pack2(float lo, float hi) {
    ull r;
    asm("mov.b64 %0, {%1, %2};" : "=l"(r) : "r"(__float_as_uint(lo)), "r"(__float_as_uint(hi)));
    return r;
}
__device__ __forceinline__ void unpack2(ull v, float& lo, float& hi) {
    uint a, b;
    asm("mov.b64 {%0, %1}, %2;" : "=r"(a), "=r"(b) : "l"(v));
    lo = __uint_as_float(a); hi = __uint_as_float(b);
}
__device__ __forceinline__ ull fma2(ull a, ull b, ull c) {
    ull d;
    asm("fma.rn.f32x2 %0, %1, %2, %3;" : "=l"(d) : "l"(a), "l"(b), "l"(c));
    return d;
}
__device__ __forceinline__ ull mul2(ull a, ull b) {
    ull d;
    asm("mul.rn.f32x2 %0, %1, %2;" : "=l"(d) : "l"(a), "l"(b));
    return d;
}
__device__ __forceinline__ ull add2(ull a, ull b) {
    ull d;
    asm("add.rn.f32x2 %0, %1, %2;" : "=l"(d) : "l"(a), "l"(b));
    return d;
}

// ---------------- GEMM: proj[r][q*4+g] = sum_k x[r][k] * W_g[q][k] ----------------
// (R14 version: 256 threads, 2 rows/thread, real distance-3 prefetch)
__global__ void __launch_bounds__(256) gemm_kernel(
    const float* __restrict__ x,
    const float* __restrict__ Wf, const float* __restrict__ Wi,
    const float* __restrict__ Wg, const float* __restrict__ Wo)
{
    __shared__ __align__(16) float ws[IN_DIM * NJ];     // [k][q*4+g], 32 KB
    const int tid = threadIdx.x;

    for (int e = tid; e < IN_DIM * NJ; e += 256) {
        int k = e >> 5, j = e & 31;
        int q = j >> 2, g = j & 3;
        const float* Wp = (g == 0) ? Wf : (g == 1) ? Wi : (g == 2) ? Wg : Wo;
        ws[e] = Wp[q * DTOT + k];
    }
    __syncthreads();

    const size_t row0 = (size_t)blockIdx.x * 512 + tid;   // second row: row0 + 256
    const float4* x0 = reinterpret_cast<const float4*>(x + row0 * IN_DIM);
    const float4* x1 = reinterpret_cast<const float4*>(x + (row0 + 256) * IN_DIM);

    ull acc0[16], acc1[16];
    #pragma unroll
    for (int p = 0; p < 16; p++) { acc0[p] = 0ull; acc1[p] = 0ull; }

    float4 abuf[4], bbuf[4];
    abuf[0] = x0[0]; bbuf[0] = x1[0];
    abuf[1] = x0[1]; bbuf[1] = x1[1];
    abuf[2] = x0[2]; bbuf[2] = x1[2];

    const int NK4 = IN_DIM / 4;   // 64
    for (int k40 = 0; k40 < NK4; k40 += 4) {
        #pragma unroll
        for (int u = 0; u < 4; u++) {
            const int k4 = k40 + u;
            float4 a = abuf[u];
            float4 b = bbuf[u];
            int kn = k4 + 3; kn = (kn > NK4 - 1) ? (NK4 - 1) : kn;
            abuf[(u + 3) & 3] = x0[kn];
            bbuf[(u + 3) & 3] = x1[kn];

            float xa[4] = {a.x, a.y, a.z, a.w};
            float xb[4] = {b.x, b.y, b.z, b.w};
            #pragma unroll
            for (int kk = 0; kk < 4; kk++) {
                const double2* wv = reinterpret_cast<const double2*>(ws + (k4 * 4 + kk) * NJ);
                ull pa = pack2(xa[kk], xa[kk]);
                ull pb = pack2(xb[kk], xb[kk]);
                #pragma unroll
                for (int p4 = 0; p4 < 8; p4++) {
                    double2 wd = wv[p4];
                    ull w0 = (ull)__double_as_longlong(wd.x);
                    ull w1 = (ull)__double_as_longlong(wd.y);
                    acc0[2*p4]   = fma2(pa, w0, acc0[2*p4]);
                    acc0[2*p4+1] = fma2(pa, w1, acc0[2*p4+1]);
                    acc1[2*p4]   = fma2(pb, w0, acc1[2*p4]);
                    acc1[2*p4+1] = fma2(pb, w1, acc1[2*p4+1]);
                }
            }
        }
    }

    double2* o0 = reinterpret_cast<double2*>(g_proj + row0 * NJ);
    double2* o1 = reinterpret_cast<double2*>(g_proj + (row0 + 256) * NJ);
    #pragma unroll
    for (int p4 = 0; p4 < 8; p4++) {
        double2 v0, v1;
        v0.x = __longlong_as_double((long long)acc0[2*p4]);
        v0.y = __longlong_as_double((long long)acc0[2*p4+1]);
        v1.x = __longlong_as_double((long long)acc1[2*p4]);
        v1.y = __longlong_as_double((long long)acc1[2*p4+1]);
        o0[p4] = v0;
        o1[p4] = v1;
    }
}

// ---------------- recurrence -------------------------------------------------------
// One warp per 4 batches, lane = sub*8 + qubit.
// Padded-window smem buffer removes all selects from the circuit product:
//   per sub: 16 slots of float4; slots 0..6 and 15 = 1.0; slot 7+q = (c_f,c_i,c_g,c_o).
//   lane q multiplies the 8 consecutive slots starting at (q==0 ? 8 : q).
// All gate math packed f32x2 where possible.
#define WSLOTS 17          // slot stride per sub (17*16B = 272B, breaks bank alignment)

__global__ void __launch_bounds__(32) recur_kernel(
    const float* __restrict__ Wf, const float* __restrict__ bf,
    const float* __restrict__ Wi, const float* __restrict__ bi,
    const float* __restrict__ Wg, const float* __restrict__ bg,
    const float* __restrict__ Wo, const float* __restrict__ bo,
    const float* __restrict__ thetas, float* __restrict__ out)
{
    __shared__ __align__(16) ull  hxp[32];                    // packed (hx,hx) per lane
    __shared__ __align__(16) float wbuf[4 * WSLOTS * 4];      // window buffers

    const int lane = threadIdx.x;
    const int q   = lane & 7;
    const int sub = lane >> 3;
    const int wg  = blockIdx.x * 4 + sub;   // batch index

    // packed recurrent weights: wh01[k] = (Wf, Wi), wh23[k] = (Wg, Wo)
    ull wh01[8], wh23[8];
    #pragma unroll
    for (int k = 0; k < 8; k++) {
        wh01[k] = pack2(Wf[q * DTOT + IN_DIM + k], Wi[q * DTOT + IN_DIM + k]);
        wh23[k] = pack2(Wg[q * DTOT + IN_DIM + k], Wo[q * DTOT + IN_DIM + k]);
    }
    const float btf = bf[q] + thetas[0 * 8 + q];
    const float bti = bi[q] + thetas[1 * 8 + q];
    const float btg = bg[q] + thetas[2 * 8 + q];
    const float bto = bo[q] + thetas[3 * 8 + q];

    // packed constants
    const ull C105 = pack2(105.0f, 105.0f);
    const ull C945 = pack2(945.0f, 945.0f);
    const ull C15  = pack2(15.0f, 15.0f);
    const ull C420 = pack2(420.0f, 420.0f);
    const ull S0 = pack2(2.1356922e-5f, 2.1356922e-5f);
    const ull S1 = pack2(-2.1081349e-4f, -2.1081349e-4f);
    const ull S2 = pack2(2.0833334e-3f, 2.0833334e-3f);
    const ull S3 = pack2(-2.0833334e-2f, -2.0833334e-2f);
    const ull S4 = pack2(0.25f, 0.25f);
    const ull HALF2 = pack2(0.5f, 0.5f);

    // init pads: slots 0..6 and 15 = 1.0 (lane p<7 -> slot p, p==7 -> slot 15)
    {
        int p = q;
        int slot = (p < 7) ? p : 15;
        *reinterpret_cast<float4*>(&wbuf[(sub * WSLOTS + slot) * 4]) =
            make_float4(1.0f, 1.0f, 1.0f, 1.0f);
    }
    hxp[lane] = 0ull;

    // pointers
    float* mySlot = &wbuf[(sub * WSLOTS + 7 + q) * 4];
    const int w0 = (q == 0) ? 8 : q;
    const float4* win = reinterpret_cast<const float4*>(&wbuf[(sub * WSLOTS + w0) * 4]);
    const ull* hgrp = &hxp[sub * 8];

    const float4* pr = reinterpret_cast<const float4*>(g_proj + (size_t)wg * TT * NJ) + q;
    float4 pbuf[4];
    pbuf[0] = pr[0];
    pbuf[1] = pr[8];
    pbuf[2] = pr[16];

    float cx = 0.f;
    float* outp = out + (size_t)wg * TT * 8 + q;

    for (int t0 = 0; t0 < TT; t0 += 4) {
        #pragma unroll
        for (int u = 0; u < 4; u++) {
            const int t = t0 + u;
            __syncwarp();   // orders prior STS (hx, windows) before this step's reads

            float4 pin = pbuf[u];
            int tn = t + 3; tn = (tn > TT - 1) ? (TT - 1) : tn;
            pbuf[(u + 3) & 3] = pr[(size_t)tn * 8];

            // read packed hidden state of my sub-batch (broadcast LDS.128 x4)
            ull hv0 = hgrp[0], hv1 = hgrp[1], hv2 = hgrp[2], hv3 = hgrp[3];
            ull hv4 = hgrp[4], hv5 = hgrp[5], hv6 = hgrp[6], hv7 = hgrp[7];

            // delta (packed): dl01 = (d_f, d_i), dl23 = (d_g, d_o)
            ull dl01 = mul2(wh01[0], hv0);
            ull dl23 = mul2(wh23[0], hv0);
            dl01 = fma2(wh01[1], hv1, dl01);  dl23 = fma2(wh23[1], hv1, dl23);
            dl01 = fma2(wh01[2], hv2, dl01);  dl23 = fma2(wh23[2], hv2, dl23);
            dl01 = fma2(wh01[3], hv3, dl01);  dl23 = fma2(wh23[3], hv3, dl23);
            dl01 = fma2(wh01[4], hv4, dl01);  dl23 = fma2(wh23[4], hv4, dl23);
            dl01 = fma2(wh01[5], hv5, dl01);  dl23 = fma2(wh23[5], hv5, dl23);
            dl01 = fma2(wh01[6], hv6, dl01);  dl23 = fma2(wh23[6], hv6, dl23);
            dl01 = fma2(wh01[7], hv7, dl01);  dl23 = fma2(wh23[7], hv7, dl23);

            float d0, d1, d2, d3;
            unpack2(dl01, d0, d1);
            unpack2(dl23, d2, d3);

            // angles and cosines
            float c0 = __cosf(pin.x + btf + d0);
            float c1 = __cosf(pin.y + bti + d1);
            float c2 = __cosf(pin.z + btg + d2);
            float c3 = __cosf(pin.w + bto + d3);

            // publish my 4 cosines to my window slot
            *reinterpret_cast<float4*>(mySlot) = make_float4(c0, c1, c2, c3);
            __syncwarp();

            // product over 8 consecutive window slots (no selects)
            float4 s0v = win[0], s1v = win[1], s2v = win[2], s3v = win[3];
            float4 s4v = win[4], s5v = win[5], s6v = win[6], s7v = win[7];
            ull a01 = mul2(pack2(s0v.x, s0v.y), pack2(s1v.x, s1v.y));
            ull b01 = mul2(pack2(s2v.x, s2v.y), pack2(s3v.x, s3v.y));
            ull e01 = mul2(pack2(s4v.x, s4v.y), pack2(s5v.x, s5v.y));
            ull f01 = mul2(pack2(s6v.x, s6v.y), pack2(s7v.x, s7v.y));
            ull m01 = mul2(mul2(a01, b01), mul2(e01, f01));
            ull a23 = mul2(pack2(s0v.z, s0v.w), pack2(s1v.z, s1v.w));
            ull b23 = mul2(pack2(s2v.z, s2v.w), pack2(s3v.z, s3v.w));
            ull e23 = mul2(pack2(s4v.z, s4v.w), pack2(s5v.z, s5v.w));
            ull f23 = mul2(pack2(s6v.z, s6v.w), pack2(s7v.z, s7v.w));
            ull m23 = mul2(mul2(a23, b23), mul2(e23, f23));

            // sigmoid packed on (m_f, m_i): 0.5 + x*poly(x^2), |x|<=1
            ull us = mul2(m01, m01);
            ull ps = fma2(us, S0, S1);
            ps = fma2(us, ps, S2);
            ps = fma2(us, ps, S3);
            ps = fma2(us, ps, S4);
            ull fi = fma2(m01, ps, HALF2);
            float f_, i_;
            unpack2(fi, f_, i_);

            // (tanh(m_g), tanh(m_o/2)) packed Pade[5/4]; sigma(o) = 0.5 + 0.5*tanh(o/2)
            float mg, mo;
            unpack2(m23, mg, mo);
            ull xt = pack2(mg, 0.5f * mo);
            ull ut = mul2(xt, xt);
            ull Nt = fma2(ut, add2(ut, C105), C945);
            Nt = mul2(xt, Nt);
            ull Dt = fma2(ut, fma2(C15, ut, C420), C945);
            float nlo, nhi, dlo, dhi;
            unpack2(Nt, nlo, nhi);
            unpack2(Dt, dlo, dhi);
            float gg = __fdividef(nlo, dlo);
            float o_ = fmaf(0.5f, __fdividef(nhi, dhi), 0.5f);

            // LSTM cell
            cx = fmaf(f_, cx, i_ * gg);          // |cx| <= 2.07
            float uu = cx * cx;
            float Nc = fmaf(uu, uu + 105.0f, 945.0f);
            float Dc = fmaf(uu, fmaf(15.0f, uu, 420.0f), 945.0f);
            float th = __fdividef(cx * Nc, Dc);
            float hx = o_ * th;

            outp[(size_t)t * 8] = hx;
            hxp[lane] = pack2(hx, hx);
        }
    }

    __syncwarp();
    float hx_final, dummy;
    unpack2(hxp[lane], hx_final, dummy);
    out[(size_t)BB * TT * 8 + (size_t)wg * 8 + q] = hx_final;                  // final hx
    out[(size_t)BB * TT * 8 + (size_t)BB * 8 + (size_t)wg * 8 + q] = cx;       // final cx
}

extern "C" void kernel_launch(void* const* d_in, const int* in_sizes, int n_in,
                              void* d_out, int out_size) {
    (void)in_sizes; (void)n_in; (void)out_size;
    const float* x  = (const float*)d_in[0];
    const float* Wf = (const float*)d_in[1]; const float* bf = (const float*)d_in[2];
    const float* Wi = (const float*)d_in[3]; const float* bi = (const float*)d_in[4];
    const float* Wg = (const float*)d_in[5]; const float* bg = (const float*)d_in[6];
    const float* Wo = (const float*)d_in[7]; const float* bo = (const float*)d_in[8];
    const float* th = (const float*)d_in[9];
    float* out = (float*)d_out;

    gemm_kernel<<<ROWS / 512, 256>>>(x, Wf, Wi, Wg, Wo);
    recur_kernel<<<BB / 4, 32>>>(Wf, bf, Wi, bi, Wg, bg, Wo, bo, th, out);
}

// round 17
// speedup vs baseline: 1.2230x; 1.0052x over previous
#include <cuda_runtime.h>

#define BB 512
#define TT 512
#define IN_DIM 256
#define NJ 32          // 4 gates * 8 qubits
#define DTOT 264
#define ROWS (BB*TT)

// scratch: input projection, layout [row][q*4+g]  (q = qubit, g = gate f,i,g,o)
__device__ float g_proj[(size_t)ROWS * NJ];

typedef unsigned long long ull;
typedef unsigned int uint;

__device__ __forceinline__ ull pack2(float lo, float hi) {
    ull r;
    asm("mov.b64 %0, {%1, %2};" : "=l"(r) : "r"(__float_as_uint(lo)), "r"(__float_as_uint(hi)));
    return r;
}
__device__ __forceinline__ void unpack2(ull v, float& lo, float& hi) {
    uint a, b;
    asm("mov.b64 {%0, %1}, %2;" : "=r"(a), "=r"(b) : "l"(v));
    lo = __uint_as_float(a); hi = __uint_as_float(b);
}
__device__ __forceinline__ ull fma2(ull a, ull b, ull c) {
    ull d;
    asm("fma.rn.f32x2 %0, %1, %2, %3;" : "=l"(d) : "l"(a), "l"(b), "l"(c));
    return d;
}
__device__ __forceinline__ ull mul2(ull a, ull b) {
    ull d;
    asm("mul.rn.f32x2 %0, %1, %2;" : "=l"(d) : "l"(a), "l"(b));
    return d;
}
__device__ __forceinline__ ull add2(ull a, ull b) {
    ull d;
    asm("add.rn.f32x2 %0, %1, %2;" : "=l"(d) : "l"(a), "l"(b));
    return d;
}

// ---------------- GEMM: proj[r][q*4+g] = sum_k x[r][k] * W_g[q][k] ----------------
// (R14 version: 256 threads, 2 rows/thread, real distance-3 prefetch)
__global__ void __launch_bounds__(256) gemm_kernel(
    const float* __restrict__ x,
    const float* __restrict__ Wf, const float* __restrict__ Wi,
    const float* __restrict__ Wg, const float* __restrict__ Wo)
{
    __shared__ __align__(16) float ws[IN_DIM * NJ];     // [k][q*4+g], 32 KB
    const int tid = threadIdx.x;

    for (int e = tid; e < IN_DIM * NJ; e += 256) {
        int k = e >> 5, j = e & 31;
        int q = j >> 2, g = j & 3;
        const float* Wp = (g == 0) ? Wf : (g == 1) ? Wi : (g == 2) ? Wg : Wo;
        ws[e] = Wp[q * DTOT + k];
    }
    __syncthreads();

    const size_t row0 = (size_t)blockIdx.x * 512 + tid;   // second row: row0 + 256
    const float4* x0 = reinterpret_cast<const float4*>(x + row0 * IN_DIM);
    const float4* x1 = reinterpret_cast<const float4*>(x + (row0 + 256) * IN_DIM);

    ull acc0[16], acc1[16];
    #pragma unroll
    for (int p = 0; p < 16; p++) { acc0[p] = 0ull; acc1[p] = 0ull; }

    float4 abuf[4], bbuf[4];
    abuf[0] = x0[0]; bbuf[0] = x1[0];
    abuf[1] = x0[1]; bbuf[1] = x1[1];
    abuf[2] = x0[2]; bbuf[2] = x1[2];

    const int NK4 = IN_DIM / 4;   // 64
    for (int k40 = 0; k40 < NK4; k40 += 4) {
        #pragma unroll
        for (int u = 0; u < 4; u++) {
            const int k4 = k40 + u;
            float4 a = abuf[u];
            float4 b = bbuf[u];
            int kn = k4 + 3; kn = (kn > NK4 - 1) ? (NK4 - 1) : kn;
            abuf[(u + 3) & 3] = x0[kn];
            bbuf[(u + 3) & 3] = x1[kn];

            float xa[4] = {a.x, a.y, a.z, a.w};
            float xb[4] = {b.x, b.y, b.z, b.w};
            #pragma unroll
            for (int kk = 0; kk < 4; kk++) {
                const double2* wv = reinterpret_cast<const double2*>(ws + (k4 * 4 + kk) * NJ);
                ull pa = pack2(xa[kk], xa[kk]);
                ull pb = pack2(xb[kk], xb[kk]);
                #pragma unroll
                for (int p4 = 0; p4 < 8; p4++) {
                    double2 wd = wv[p4];
                    ull w0 = (ull)__double_as_longlong(wd.x);
                    ull w1 = (ull)__double_as_longlong(wd.y);
                    acc0[2*p4]   = fma2(pa, w0, acc0[2*p4]);
                    acc0[2*p4+1] = fma2(pa, w1, acc0[2*p4+1]);
                    acc1[2*p4]   = fma2(pb, w0, acc1[2*p4]);
                    acc1[2*p4+1] = fma2(pb, w1, acc1[2*p4+1]);
                }
            }
        }
    }

    double2* o0 = reinterpret_cast<double2*>(g_proj + row0 * NJ);
    double2* o1 = reinterpret_cast<double2*>(g_proj + (row0 + 256) * NJ);
    #pragma unroll
    for (int p4 = 0; p4 < 8; p4++) {
        double2 v0, v1;
        v0.x = __longlong_as_double((long long)acc0[2*p4]);
        v0.y = __longlong_as_double((long long)acc0[2*p4+1]);
        v1.x = __longlong_as_double((long long)acc1[2*p4]);
        v1.y = __longlong_as_double((long long)acc1[2*p4+1]);
        o0[p4] = v0;
        o1[p4] = v1;
    }
}

// ---------------- recurrence -------------------------------------------------------
// One warp per 4 batches, lane = sub*8 + qubit.
// Padded-window smem buffer removes all selects from the circuit product:
//   per sub: 16 slots of float4; slots 0..6 and 15 = 1.0; slot 7+q = (c_f,c_i,c_g,c_o).
//   lane q multiplies the 8 consecutive slots starting at (q==0 ? 8 : q).
// All gate math packed f32x2 where possible.
#define WSLOTS 17          // slot stride per sub (17*16B = 272B, breaks bank alignment)

__global__ void __launch_bounds__(32) recur_kernel(
    const float* __restrict__ Wf, const float* __restrict__ bf,
    const float* __restrict__ Wi, const float* __restrict__ bi,
    const float* __restrict__ Wg, const float* __restrict__ bg,
    const float* __restrict__ Wo, const float* __restrict__ bo,
    const float* __restrict__ thetas, float* __restrict__ out)
{
    __shared__ __align__(16) ull  hxp[32];                    // packed (hx,hx) per lane
    __shared__ __align__(16) float wbuf[4 * WSLOTS * 4];      // window buffers

    const int lane = threadIdx.x;
    const int q   = lane & 7;
    const int sub = lane >> 3;
    const int wg  = blockIdx.x * 4 + sub;   // batch index

    // packed recurrent weights: wh01[k] = (Wf, Wi), wh23[k] = (Wg, Wo)
    ull wh01[8], wh23[8];
    #pragma unroll
    for (int k = 0; k < 8; k++) {
        wh01[k] = pack2(Wf[q * DTOT + IN_DIM + k], Wi[q * DTOT + IN_DIM + k]);
        wh23[k] = pack2(Wg[q * DTOT + IN_DIM + k], Wo[q * DTOT + IN_DIM + k]);
    }
    const float btf = bf[q] + thetas[0 * 8 + q];
    const float bti = bi[q] + thetas[1 * 8 + q];
    const float btg = bg[q] + thetas[2 * 8 + q];
    const float bto = bo[q] + thetas[3 * 8 + q];

    // packed constants
    const ull C105 = pack2(105.0f, 105.0f);
    const ull C945 = pack2(945.0f, 945.0f);
    const ull C15  = pack2(15.0f, 15.0f);
    const ull C420 = pack2(420.0f, 420.0f);
    const ull S0 = pack2(2.1356922e-5f, 2.1356922e-5f);
    const ull S1 = pack2(-2.1081349e-4f, -2.1081349e-4f);
    const ull S2 = pack2(2.0833334e-3f, 2.0833334e-3f);
    const ull S3 = pack2(-2.0833334e-2f, -2.0833334e-2f);
    const ull S4 = pack2(0.25f, 0.25f);
    const ull HALF2 = pack2(0.5f, 0.5f);

    // init pads: slots 0..6 and 15 = 1.0 (lane p<7 -> slot p, p==7 -> slot 15)
    {
        int p = q;
        int slot = (p < 7) ? p : 15;
        *reinterpret_cast<float4*>(&wbuf[(sub * WSLOTS + slot) * 4]) =
            make_float4(1.0f, 1.0f, 1.0f, 1.0f);
    }
    hxp[lane] = 0ull;

    // pointers
    float* mySlot = &wbuf[(sub * WSLOTS + 7 + q) * 4];
    const int w0 = (q == 0) ? 8 : q;
    const float4* win = reinterpret_cast<const float4*>(&wbuf[(sub * WSLOTS + w0) * 4]);
    const ull* hgrp = &hxp[sub * 8];

    const float4* pr = reinterpret_cast<const float4*>(g_proj + (size_t)wg * TT * NJ) + q;
    float4 pbuf[4];
    pbuf[0] = pr[0];
    pbuf[1] = pr[8];
    pbuf[2] = pr[16];

    float cx = 0.f;
    float* outp = out + (size_t)wg * TT * 8 + q;

    for (int t0 = 0; t0 < TT; t0 += 4) {
        #pragma unroll
        for (int u = 0; u < 4; u++) {
            const int t = t0 + u;
            __syncwarp();   // orders prior STS (hx, windows) before this step's reads

            float4 pin = pbuf[u];
            int tn = t + 3; tn = (tn > TT - 1) ? (TT - 1) : tn;
            pbuf[(u + 3) & 3] = pr[(size_t)tn * 8];

            // read packed hidden state of my sub-batch (broadcast LDS.128 x4)
            ull hv0 = hgrp[0], hv1 = hgrp[1], hv2 = hgrp[2], hv3 = hgrp[3];
            ull hv4 = hgrp[4], hv5 = hgrp[5], hv6 = hgrp[6], hv7 = hgrp[7];

            // delta (packed): dl01 = (d_f, d_i), dl23 = (d_g, d_o)
            ull dl01 = mul2(wh01[0], hv0);
            ull dl23 = mul2(wh23[0], hv0);
            dl01 = fma2(wh01[1], hv1, dl01);  dl23 = fma2(wh23[1], hv1, dl23);
            dl01 = fma2(wh01[2], hv2, dl01);  dl23 = fma2(wh23[2], hv2, dl23);
            dl01 = fma2(wh01[3], hv3, dl01);  dl23 = fma2(wh23[3], hv3, dl23);
            dl01 = fma2(wh01[4], hv4, dl01);  dl23 = fma2(wh23[4], hv4, dl23);
            dl01 = fma2(wh01[5], hv5, dl01);  dl23 = fma2(wh23[5], hv5, dl23);
            dl01 = fma2(wh01[6], hv6, dl01);  dl23 = fma2(wh23[6], hv6, dl23);
            dl01 = fma2(wh01[7], hv7, dl01);  dl23 = fma2(wh23[7], hv7, dl23);

            float d0, d1, d2, d3;
            unpack2(dl01, d0, d1);
            unpack2(dl23, d2, d3);

            // angles and cosines
            float c0 = __cosf(pin.x + btf + d0);
            float c1 = __cosf(pin.y + bti + d1);
            float c2 = __cosf(pin.z + btg + d2);
            float c3 = __cosf(pin.w + bto + d3);

            // publish my 4 cosines to my window slot
            *reinterpret_cast<float4*>(mySlot) = make_float4(c0, c1, c2, c3);
            __syncwarp();

            // product over 8 consecutive window slots (no selects)
            float4 s0v = win[0], s1v = win[1], s2v = win[2], s3v = win[3];
            float4 s4v = win[4], s5v = win[5], s6v = win[6], s7v = win[7];
            ull a01 = mul2(pack2(s0v.x, s0v.y), pack2(s1v.x, s1v.y));
            ull b01 = mul2(pack2(s2v.x, s2v.y), pack2(s3v.x, s3v.y));
            ull e01 = mul2(pack2(s4v.x, s4v.y), pack2(s5v.x, s5v.y));
            ull f01 = mul2(pack2(s6v.x, s6v.y), pack2(s7v.x, s7v.y));
            ull m01 = mul2(mul2(a01, b01), mul2(e01, f01));
            ull a23 = mul2(pack2(s0v.z, s0v.w), pack2(s1v.z, s1v.w));
            ull b23 = mul2(pack2(s2v.z, s2v.w), pack2(s3v.z, s3v.w));
            ull e23 = mul2(pack2(s4v.z, s4v.w), pack2(s5v.z, s5v.w));
            ull f23 = mul2(pack2(s6v.z, s6v.w), pack2(s7v.z, s7v.w));
            ull m23 = mul2(mul2(a23, b23), mul2(e23, f23));

            // sigmoid packed on (m_f, m_i): 0.5 + x*poly(x^2), |x|<=1
            ull us = mul2(m01, m01);
            ull ps = fma2(us, S0, S1);
            ps = fma2(us, ps, S2);
            ps = fma2(us, ps, S3);
            ps = fma2(us, ps, S4);
            ull fi = fma2(m01, ps, HALF2);
            float f_, i_;
            unpack2(fi, f_, i_);

            // (tanh(m_g), tanh(m_o/2)) packed Pade[5/4]; sigma(o) = 0.5 + 0.5*tanh(o/2)
            float mg, mo;
            unpack2(m23, mg, mo);
            ull xt = pack2(mg, 0.5f * mo);
            ull ut = mul2(xt, xt);
            ull Nt = fma2(ut, add2(ut, C105), C945);
            Nt = mul2(xt, Nt);
            ull Dt = fma2(ut, fma2(C15, ut, C420), C945);
            float nlo, nhi, dlo, dhi;
            unpack2(Nt, nlo, nhi);
            unpack2(Dt, dlo, dhi);
            float gg = __fdividef(nlo, dlo);
            float o_ = fmaf(0.5f, __fdividef(nhi, dhi), 0.5f);

            // LSTM cell
            cx = fmaf(f_, cx, i_ * gg);          // |cx| <= 2.07
            float uu = cx * cx;
            float Nc = fmaf(uu, uu + 105.0f, 945.0f);
            float Dc = fmaf(uu, fmaf(15.0f, uu, 420.0f), 945.0f);
            float th = __fdividef(cx * Nc, Dc);
            float hx = o_ * th;

            outp[(size_t)t * 8] = hx;
            hxp[lane] = pack2(hx, hx);
        }
    }

    __syncwarp();
    float hx_final, dummy;
    unpack2(hxp[lane], hx_final, dummy);
    out[(size_t)BB * TT * 8 + (size_t)wg * 8 + q] = hx_final;                  // final hx
    out[(size_t)BB * TT * 8 + (size_t)BB * 8 + (size_t)wg * 8 + q] = cx;       // final cx
}

extern "C" void kernel_launch(void* const* d_in, const int* in_sizes, int n_in,
                              void* d_out, int out_size) {
    (void)in_sizes; (void)n_in; (void)out_size;
    const float* x  = (const float*)d_in[0];
    const float* Wf = (const float*)d_in[1]; const float* bf = (const float*)d_in[2];
    const float* Wi = (const float*)d_in[3]; const float* bi = (const float*)d_in[4];
    const float* Wg = (const float*)d_in[5]; const float* bg = (const float*)d_in[6];
    const float* Wo = (const float*)d_in[7]; const float* bo = (const float*)d_in[8];
    const float* th = (const float*)d_in[9];
    float* out = (float*)d_out;

    gemm_kernel<<<ROWS / 512, 256>>>(x, Wf, Wi, Wg, Wo);
    recur_kernel<<<BB / 4, 32>>>(Wf, bf, Wi, bi, Wg, bg, Wo, bo, th, out);
}